// round 17
// baseline (speedup 1.0000x reference)
#include <cuda_runtime.h>
#include <cuda_bf16.h>
#include <math.h>
#include <stdint.h>

#define N_SEQS   2048
#define SEQ_LEN  512
#define N_AA     20
#define M_MI     100
#define N_PAIRS  4950                    // 100*99/2 upper triangle
#define OUT_PSSM 0
#define OUT_CONS (SEQ_LEN * N_AA)        // 10240
#define OUT_MI   (OUT_CONS + SEQ_LEN)    // 10752
#define OUT_TOTAL (OUT_MI + SEQ_LEN * SEQ_LEN)  // 272896

#define MI_CTAS   592                    // 4 per SM exactly -> perfect balance
#define MI_WARPS  (MI_CTAS * 8)          // 4736; warp handles pid, pid+4736
#define AUX_CTAS  64                     // zero + pssm CTAs
#define MEGA_CTAS (MI_CTAS + AUX_CTAS)   // 656

// Scratch (no dynamic allocation allowed)
__device__ unsigned char g_colpack[128 * N_SEQS];    // column-major int8 msa[:, :128] (100 used)
__device__ int           g_part[16][SEQ_LEN][21];    // count partials (plain stores, no zeroing)
__device__ float         g_lut[2049];                // log2(0..2048), written once by prep

// ---------------------------------------------------------------------------
// PREP (node 1): pack + per-position counts in one msa pass. CTA (0,0) also
// writes the global log2 LUT. grid (16,16) x 256.
// ---------------------------------------------------------------------------
__global__ __launch_bounds__(256) void prep_kernel(const int* __restrict__ msa) {
    __shared__ int cnt[8][32][21];     // [warp][lane(col)][symbol]
    int tid = threadIdx.x, lane = tid & 31, w = tid >> 5;
    for (int v = tid; v < 8 * 32 * 21; v += 256) ((int*)cnt)[v] = 0;

    if (blockIdx.x == 0 && blockIdx.y == 0) {       // one CTA fills the LUT
        for (int v = tid; v < 2049; v += 256) g_lut[v] = log2f((float)v);
    }
    __syncthreads();

    int col   = blockIdx.x * 32 + lane;
    int rbase = blockIdx.y * 128 + w * 16;

    int vals[16];
#pragma unroll
    for (int s = 0; s < 16; s++)
        vals[s] = msa[(rbase + s) * SEQ_LEN + col];    // coalesced 128B per warp

    int* my = cnt[w][lane];
#pragma unroll
    for (int s = 0; s < 16; s++) my[vals[s]] += 1;     // private replica: plain RMW

    if (col < M_MI) {                                   // pack 16 rows -> uint4
        uint32_t pk[4];
#pragma unroll
        for (int g = 0; g < 4; g++)
            pk[g] = (uint32_t)vals[4 * g] | ((uint32_t)vals[4 * g + 1] << 8) |
                    ((uint32_t)vals[4 * g + 2] << 16) | ((uint32_t)vals[4 * g + 3] << 24);
        *(uint4*)&g_colpack[col * N_SEQS + rbase] = make_uint4(pk[0], pk[1], pk[2], pk[3]);
    }
    __syncthreads();

    for (int v = tid; v < 32 * 21; v += 256) {
        int l = v / 21, c = v % 21;
        int s = 0;
#pragma unroll
        for (int ww = 0; ww < 8; ww++) s += cnt[ww][l][c];
        g_part[blockIdx.y][blockIdx.x * 32 + l][c] = s;   // plain store
    }
}

// ---------------------------------------------------------------------------
// MEGA (node 2): heterogeneous grid, ordering vs prep via kernel boundary.
//   CTAs 0..591   : mi — PERSISTENT PAIRS: warp gw handles pid = gw and
//                   gw + 4736 (214 warps get a 2nd pair -> short balanced
//                   tail). 592 CTAs = exactly 4/SM -> even placement.
//   CTAs 592..655 : zero the COMPLEMENT of mi's write set, then pssm +
//                   conservation (one warp per position). Hidden under mi.
// ---------------------------------------------------------------------------
__global__ __launch_bounds__(256) void mega_kernel(float* __restrict__ out,
                                                   const float* __restrict__ pc) {
    __shared__ int   hist[8][400];
    __shared__ float slra[8][20];
    __shared__ float slcb[8][20];

    int b = blockIdx.x;
    int tid = threadIdx.x, lane = tid & 31, w = tid >> 5;
    float* mi_out = out + OUT_MI;

    if (b >= MI_CTAS) {
        // ================== ZERO-COMPLEMENT + PSSM branch ==================
        int bb = b - MI_CTAS;

        // Zero the complement of mi's write set (63136 tasks / 16384 threads)
        for (int t = bb * 256 + tid; t < 63136; t += AUX_CTAS * 256) {
            if (t < 52736) {                               // rows 100..511, all cols
                int r = 100 + (t >> 7);
                ((float4*)mi_out)[r * 128 + (t & 127)] = make_float4(0.f, 0.f, 0.f, 0.f);
            } else if (t < 63036) {                        // rows 0..99, cols 100..511
                int u = t - 52736;
                int r = u / 103, c4 = 25 + (u - r * 103);
                ((float4*)mi_out)[r * 128 + c4] = make_float4(0.f, 0.f, 0.f, 0.f);
            } else {                                       // diagonal d<100
                int dd = t - 63036;
                mi_out[dd * SEQ_LEN + dd] = 0.f;
            }
        }

        // pssm + conservation: warp w -> position bb*8 + w  (64*8 = 512)
        int p = bb * 8 + w;
        int ct = 0;
        if (lane < 20) {
#pragma unroll
            for (int k = 0; k < 16; k++) ct += g_part[k][p][lane];
        }
        int t = ct;
#pragma unroll
        for (int off = 16; off; off >>= 1) t += __shfl_xor_sync(0xffffffffu, t, off);
        int total = t;

        float pcount = 0.01f * pc[0];
        float inv_den = 1.0f / ((float)N_SEQS + pcount * 20.0f);
        float tinv = 1.0f / fmaxf((float)total, 1.0f);

        float ent = 0.0f;
        if (lane < 20) {
            float freq = ((float)ct + pcount) * inv_den;
            out[OUT_PSSM + p * 20 + lane] = logf(freq * 20.0f + 1e-10f);
            float f = (float)ct * tinv;
            ent = -f * log2f(f + 1e-10f);
        }
#pragma unroll
        for (int off = 16; off; off >>= 1) ent += __shfl_xor_sync(0xffffffffu, ent, off);
        if (lane == 0)
            out[OUT_CONS + p] = (total > 0) ? (1.0f - ent * (1.0f / 4.321928094887362f)) : 0.0f;
        return;
    }

    // ===================== MI branch (persistent pairs) =====================
    int wid = w;
    int gw = b * 8 + wid;
    int* h = hist[wid];

    for (int pid = gw; pid < N_PAIRS; pid += MI_WARPS) {
        // Decode upper-triangle pair index -> (i, j), i < j; T(i) = i*(199-i)/2
        float d = sqrtf(39601.0f - 8.0f * (float)pid);
        int i = (int)((199.0f - d) * 0.5f);
        if (i < 0) i = 0;
        if (i > 98) i = 98;
        while ((((i + 1) * (199 - (i + 1))) >> 1) <= pid) ++i;
        while (((i * (199 - i)) >> 1) > pid) --i;
        int j = pid - ((i * (199 - i)) >> 1) + i + 1;

        for (int v = lane; v < 100; v += 32)              // 400 ints = 100 int4
            ((int4*)h)[v] = make_int4(0, 0, 0, 0);
        __syncwarp();

        const uint4* ca = (const uint4*)(g_colpack + i * N_SEQS);
        const uint4* cb = (const uint4*)(g_colpack + j * N_SEQS);
#pragma unroll
        for (int it = 0; it < 4; it++) {                // 4 x LDG.128 per operand
            uint4 va = ca[lane + 32 * it];
            uint4 vb = cb[lane + 32 * it];
            const uint32_t wa_[4] = {va.x, va.y, va.z, va.w};
            const uint32_t wb_[4] = {vb.x, vb.y, vb.z, vb.w};
#pragma unroll
            for (int q = 0; q < 4; q++) {
                uint32_t wa = wa_[q], wb = wb_[q];
#pragma unroll
                for (int s = 0; s < 4; s++) {
                    int a  = __byte_perm(wa, 0, 0x4440 | s);  // byte s of wa
                    int bb = __byte_perm(wb, 0, 0x4440 | s);  // byte s of wb
                    if (a < 20 && bb < 20)
                        atomicAdd(&h[a * 20 + bb], 1);
                }
            }
        }
        __syncwarp();

        // Integer marginals over the 20x20 block (log2 via L2-resident g_lut)
        int rs = 0, cs = 0;
        if (lane < 20) {
#pragma unroll
            for (int bq = 0; bq < 20; bq++) { rs += h[lane * 20 + bq]; cs += h[bq * 20 + lane]; }
            slra[wid][lane] = __ldg(&g_lut[rs]);
            slcb[wid][lane] = __ldg(&g_lut[cs]);
        }
        int tv = (lane < 20) ? rs : 0;
#pragma unroll
        for (int off = 16; off; off >>= 1) tv += __shfl_xor_sync(0xffffffffu, tv, off);
        int tot = tv;
        __syncwarp();

        int tots = (tot > 0) ? tot : 1;
        float lt = __ldg(&g_lut[tots]);
        float acc = 0.0f;
        for (int c = lane; c < 400; c += 32) {
            int H = h[c];
            if (H > 0) {
                int a = (c * 3277) >> 16;   // c / 20 for c < 400
                int bq = c - a * 20;
                acc += (float)H * (__ldg(&g_lut[H]) - slra[wid][a] - slcb[wid][bq] + lt);
            }
        }
#pragma unroll
        for (int off = 16; off; off >>= 1) acc += __shfl_xor_sync(0xffffffffu, acc, off);

        if (lane == 0) {
            float mi = (tot > 0) ? acc / (float)tots : 0.0f;
            mi_out[i * SEQ_LEN + j] = mi;
            mi_out[j * SEQ_LEN + i] = mi;
        }
        __syncwarp();
    }
}

// ---------------------------------------------------------------------------
// Launch: SINGLE stream, TWO nodes. prep -> mega (zero + pssm hidden in mega).
// ---------------------------------------------------------------------------
extern "C" void kernel_launch(void* const* d_in, const int* in_sizes, int n_in,
                              void* d_out, int out_size) {
    const int*   msa = (const int*)d_in[0];
    const float* pc  = (const float*)d_in[1];
    float*       out = (float*)d_out;

    prep_kernel<<<dim3(16, 16), 256>>>(msa);        // pack + counts + lut
    mega_kernel<<<MEGA_CTAS, 256>>>(out, pc);       // mi + (zero + pssm hidden)
}